// round 4
// baseline (speedup 1.0000x reference)
#include <cuda_runtime.h>

// Problem constants (B=256, S=1024, H=128)
#define B_TOT 256
#define SEQ   1024
#define HID   128
#define NTHR  384            // one thread per W_hh row
#define BPC   2              // batches per CTA
#define NCTA  (B_TOT / BPC)  // 128 CTAs -> 1 wave on 148 SMs

// Packed 2xfp32 FMA (Blackwell f32x2; ptxas won't auto-fuse from C++)
__device__ __forceinline__ unsigned long long ffma2(unsigned long long a,
                                                    unsigned long long b,
                                                    unsigned long long c) {
    unsigned long long d;
    asm("fma.rn.f32x2 %0, %1, %2, %3;" : "=l"(d) : "l"(a), "l"(b), "l"(c));
    return d;
}

__device__ __forceinline__ float2 unpack_f32x2(unsigned long long v) {
    float2 f;
    asm("mov.b64 {%0, %1}, %2;" : "=f"(f.x), "=f"(f.y) : "l"(v));
    return f;
}

__device__ __forceinline__ float sigmoid_acc(float x) {
    return 1.0f / (1.0f + __expf(-x));   // __expf rel err ~1e-6
}

__device__ __forceinline__ float tanh_acc(float x) {
    float ax = fabsf(x);
    float e  = __expf(-2.0f * ax);
    float r  = (1.0f - e) / (1.0f + e);
    return copysignf(r, x);
}

// ---- matvec for batch P at time S_IDX; rz rows -> smem, n rows -> registers ----
#define MATVEC(P, S_IDX, PEND_GHN, PEND_IN)                                    \
    do {                                                                       \
        unsigned long long a0 = 0ull, a1 = 0ull, a2 = 0ull, a3 = 0ull;         \
        const ulonglong2* hp = reinterpret_cast<const ulonglong2*>(h_sh[P]);   \
        _Pragma("unroll")                                                      \
        for (int i = 0; i < HID / 8; i++) {                                    \
            ulonglong2 v0 = hp[2 * i];                                         \
            ulonglong2 v1 = hp[2 * i + 1];                                     \
            a0 = ffma2(w2[4 * i + 0], v0.x, a0);                               \
            a1 = ffma2(w2[4 * i + 1], v0.y, a1);                               \
            a2 = ffma2(w2[4 * i + 2], v1.x, a2);                               \
            a3 = ffma2(w2[4 * i + 3], v1.y, a3);                               \
        }                                                                      \
        float2 f0 = unpack_f32x2(a0), f1 = unpack_f32x2(a1);                   \
        float2 f2 = unpack_f32x2(a2), f3 = unpack_f32x2(a3);                   \
        float d  = ((f0.x + f0.y) + (f1.x + f1.y)) +                           \
                   ((f2.x + f2.y) + (f3.x + f3.y));                            \
        float gh = d + bhh_t;                                                  \
        float gi = fmaf(x_sh[P][S_IDX], wih_t, bih_t);                         \
        if (t < 2 * HID) rz_sh[P][t] = gh + gi;                                \
        else { PEND_GHN = gh; PEND_IN = gi; }                                  \
    } while (0)

// ---- gate update for batch Q (n-row threads only); h kept in register ----
#define GATES(Q, PEND_GHN, PEND_IN, HREG)                                      \
    do {                                                                       \
        if (t >= 2 * HID) {                                                    \
            float r  = sigmoid_acc(rz_sh[Q][jg]);                              \
            float z  = sigmoid_acc(rz_sh[Q][HID + jg]);                        \
            float n  = tanh_acc(PEND_IN + r * PEND_GHN);                       \
            float hn = n + z * (HREG - n);                                     \
            HREG = hn;                                                         \
            h_sh[Q][jg] = hn;                                                  \
        }                                                                      \
    } while (0)

__global__ void __launch_bounds__(NTHR, 1)
gru_fused_kernel(const float* __restrict__ x,     // [B, S]
                 const float* __restrict__ w_ih,  // [3H]
                 const float* __restrict__ w_hh,  // [3H, H]
                 const float* __restrict__ b_ih,  // [3H]
                 const float* __restrict__ b_hh,  // [3H]
                 const float* __restrict__ w_fc,  // [H]
                 const float* __restrict__ b_fc,  // [1]
                 float* __restrict__ out)         // [B]
{
    __shared__ __align__(16) float x_sh[BPC][SEQ];     // 8 KB
    __shared__ __align__(16) float h_sh[BPC][HID];     // hidden states
    __shared__ __align__(16) float rz_sh[BPC][2 * HID];// r/z pre-activations

    const int t  = threadIdx.x;       // row of W_hh
    const int b0 = blockIdx.x * BPC;
    const int jg = t - 2 * HID;       // hidden unit for n-row (gate) threads

    // One W_hh row in registers (64 x f32x2 = 128 regs), reused 2048 times
    unsigned long long w2[HID / 2];
    {
        const ulonglong2* wr = reinterpret_cast<const ulonglong2*>(w_hh + t * HID);
        #pragma unroll
        for (int i = 0; i < HID / 4; i++) {
            ulonglong2 v = wr[i];
            w2[2 * i]     = v.x;
            w2[2 * i + 1] = v.y;
        }
    }
    const float wih_t = w_ih[t];
    const float bih_t = b_ih[t];
    const float bhh_t = b_hh[t];

    // stage x (rows b0, b0+1 are contiguous in gmem)
    for (int i = t; i < BPC * SEQ; i += NTHR)
        (&x_sh[0][0])[i] = x[b0 * SEQ + i];
    if (t < BPC * HID)
        h_sh[t >> 7][t & (HID - 1)] = 0.0f;

    // per-batch register state held by the n-row (gate) threads
    float ghn0 = 0.f, in0 = 0.f, hreg0 = 0.f;
    float ghn1 = 0.f, in1 = 0.f, hreg1 = 0.f;
    __syncthreads();

    // prologue: matvec b0 @ s=0 (h0 = 0)
    MATVEC(0, 0, ghn0, in0);
    __syncthreads();

    for (int s = 0; s < SEQ; s++) {
        // region A: matvec b1 @ s  ||  gates b0 @ s
        MATVEC(1, s, ghn1, in1);
        GATES(0, ghn0, in0, hreg0);
        __syncthreads();

        // region B: matvec b0 @ s+1  ||  gates b1 @ s
        if (s + 1 < SEQ)
            MATVEC(0, s + 1, ghn0, in0);
        GATES(1, ghn1, in1, hreg1);
        __syncthreads();
    }

    // ---- fused fc1: out[b] = relu(hT) . w_fc + b_fc ----
    if (t >= 2 * HID) {
        float wf = w_fc[jg];
        rz_sh[0][jg] = fmaxf(hreg0, 0.0f) * wf;
        rz_sh[1][jg] = fmaxf(hreg1, 0.0f) * wf;
    }
    __syncthreads();
    if (t < BPC) {
        float acc = b_fc[0];
        #pragma unroll 8
        for (int k = 0; k < HID; k++)
            acc += rz_sh[t][k];
        out[b0 + t] = acc;
    }
}

extern "C" void kernel_launch(void* const* d_in, const int* in_sizes, int n_in,
                              void* d_out, int out_size) {
    const float* x    = (const float*)d_in[0];
    const float* w_ih = (const float*)d_in[1];
    const float* w_hh = (const float*)d_in[2];
    const float* b_ih = (const float*)d_in[3];
    const float* b_hh = (const float*)d_in[4];
    const float* w_fc = (const float*)d_in[5];
    const float* b_fc = (const float*)d_in[6];
    float* out = (float*)d_out;

    gru_fused_kernel<<<NCTA, NTHR>>>(x, w_ih, w_hh, b_ih, b_hh, w_fc, b_fc, out);
}